// round 7
// baseline (speedup 1.0000x reference)
#include <cuda_runtime.h>

#define NL      32
#define NF      720
#define NSUB    60
#define DTF     60.0f
#define CHUNK   20
#define NCHUNK  36             // 35 full chunks + last of 19 (35*20=700, 719-700=19)
#define NCOLS   NL             // 32 blocks computing P^CHUNK columns
#define NDBLK   (NCHUNK - 1)   // 35 blocks computing chunk sums D_c
#define PH1     (NCOLS + NDBLK)    // 67 phase-1 blocks
#define GRIDM   (PH1 + 1)          // 68: last block runs the carry chain

typedef unsigned long long u64;

// Persistent scratch (__device__ globals per allocation rules)
__device__ float2   g_P [NL * NL];
__device__ float2   g_g0[NL];
__device__ float2   g_g1[NL];
__device__ float2   g_PL[NL * NL];
__device__ float2   g_D [NDBLK][NL];
__device__ float2   g_C [NCHUNK][NL];
__device__ unsigned g_counter;
__device__ unsigned g_flag;

// ---- packed f32x2 helpers (Blackwell FFMA2) --------------------------------
__device__ __forceinline__ u64 pk2(float lo, float hi) {
    u64 r; asm("mov.b64 %0, {%1, %2};" : "=l"(r) : "f"(lo), "f"(hi)); return r;
}
__device__ __forceinline__ void upk2(float& lo, float& hi, u64 v) {
    asm("mov.b64 {%0, %1}, %2;" : "=f"(lo), "=f"(hi) : "l"(v));
}
__device__ __forceinline__ void ffma2(u64& d, u64 a, u64 b) {
    asm("fma.rn.f32x2 %0, %1, %2, %3;" : "=l"(d) : "l"(a), "l"(b), "l"(d));
}
__device__ __forceinline__ u64 add2(u64 a, u64 b) {
    u64 r; asm("add.rn.f32x2 %0, %1, %2;" : "=l"(r) : "l"(a), "l"(b)); return r;
}

// load this lane's FULL packed row of a row-major complex matrix
__device__ __forceinline__ void load_row(const float2* __restrict__ M, int r,
                                         u64* Pxx, u64* Pyy)
{
    #pragma unroll
    for (int j = 0; j < NL; ++j) {
        float2 p = M[r * NL + j];
        Pxx[j] = pk2(p.x, p.x);
        Pyy[j] = pk2(p.y, p.y);
    }
}

// ---------------------------------------------------------------------------
// Single-warp matvec: lane r computes row r of  wnxt = P*wcur + f.
// wcur read as packed (wr,wi) via LDS.128 — no shuffles, no packs.
// One __syncwarp per step (double-buffered).
// ---------------------------------------------------------------------------
__device__ __forceinline__ void wmatvec(const u64* __restrict__ Pxx,
                                        const u64* __restrict__ Pyy,
                                        const float2* __restrict__ wcur,
                                        float2* __restrict__ wnxt,
                                        int lane, float fr, float fi)
{
    const ulonglong2* wv = reinterpret_cast<const ulonglong2*>(wcur);
    u64 a1[4], a2[4];
    a1[0] = pk2(fr, fi); a1[1] = 0ull; a1[2] = 0ull; a1[3] = 0ull;
    a2[0] = 0ull;        a2[1] = 0ull; a2[2] = 0ull; a2[3] = 0ull;

    #pragma unroll
    for (int jj = 0; jj < 16; ++jj) {            // 16 x LDS.128
        ulonglong2 bb = wv[jj];                  // (w[2jj], w[2jj+1]) packed
        ffma2(a1[jj & 3], Pxx[2*jj  ], bb.x);
        ffma2(a2[jj & 3], Pyy[2*jj  ], bb.x);
        ffma2(a1[jj & 3], Pxx[2*jj+1], bb.y);
        ffma2(a2[jj & 3], Pyy[2*jj+1], bb.y);
    }
    u64 s1 = add2(add2(a1[0], a1[1]), add2(a1[2], a1[3]));
    u64 s2 = add2(add2(a2[0], a2[1]), add2(a2[2], a2[3]));
    float s1r, s1i, s2r, s2i;
    upk2(s1r, s1i, s1);
    upk2(s2r, s2i, s2);
    wnxt[lane] = make_float2(s1r - s2i, s1i + s2r);
    __syncwarp();
}

// ---------------------------------------------------------------------------
// Kernel 1: setup. 33 single-warp blocks (one SM each).
//   block b < 32 : column b of P = M^60
//   block 32     : g0, g1 + sync-variable reset
// ---------------------------------------------------------------------------
__global__ void __launch_bounds__(32, 1)
setup_kernel(const float* __restrict__ pk, const float* __restrict__ fc)
{
    const unsigned FULL = 0xffffffffu;
    const int lane = threadIdx.x;
    const int b    = blockIdx.x;

    const float kin  = expf(pk[2 * lane]);
    const float kout = expf(pk[2 * lane + 1]);
    const float dtf  = DTF * fc[0];

    const float ca  = (lane > 0)      ? DTF * kin  : 0.0f;
    const float cb  = (lane < NL - 1) ? DTF * kout : 0.0f;
    const float cmr = 1.0f - DTF * (((lane > 0) ? kin : 0.0f) + kout);

    if (b < NL) {
        float xr = (lane == b) ? 1.0f : 0.0f;
        float xi = 0.0f;
        #pragma unroll 4
        for (int s = 0; s < NSUB; ++s) {
            float xr_up = __shfl_up_sync  (FULL, xr, 1);
            float xi_up = __shfl_up_sync  (FULL, xi, 1);
            float xr_dn = __shfl_down_sync(FULL, xr, 1);
            float xi_dn = __shfl_down_sync(FULL, xi, 1);
            float yr = cmr * xr + dtf * xi + ca * xr_up + cb * xr_dn;
            float yi = cmr * xi - dtf * xr + ca * xi_up + cb * xi_dn;
            xr = yr; xi = yi;
        }
        g_P[lane * NL + b] = make_float2(xr, xi);
    } else {
        if (lane == 0) { g_counter = 0; g_flag = 0; }
        const float scale = DTF * expf(pk[0]);
        float y0r = 0.f, y0i = 0.f, y1r = 0.f, y1i = 0.f;
        for (int j = 0; j < NSUB; ++j) {
            float a0r = __shfl_up_sync  (FULL, y0r, 1);
            float a0i = __shfl_up_sync  (FULL, y0i, 1);
            float a1r = __shfl_up_sync  (FULL, y1r, 1);
            float a1i = __shfl_up_sync  (FULL, y1i, 1);
            float b0r = __shfl_down_sync(FULL, y0r, 1);
            float b0i = __shfl_down_sync(FULL, y0i, 1);
            float b1r = __shfl_down_sync(FULL, y1r, 1);
            float b1i = __shfl_down_sync(FULL, y1i, 1);

            float n0r = cmr * y0r + dtf * y0i + ca * a0r + cb * b0r;
            float n0i = cmr * y0i - dtf * y0r + ca * a0i + cb * b0i;
            float n1r = cmr * y1r + dtf * y1i + ca * a1r + cb * b1r;
            float n1i = cmr * y1i - dtf * y1r + ca * a1i + cb * b1i;

            const float aa = (float)j / (float)NSUB;
            if (lane == 0) {
                n0r += scale * (1.0f - aa);
                n1r += scale * aa;
            }
            y0r = n0r; y0i = n0i; y1r = n1r; y1i = n1i;
        }
        g_g0[lane] = make_float2(y0r, y0i);
        g_g1[lane] = make_float2(y1r, y1i);
    }
}

// ---------------------------------------------------------------------------
// Kernel 2: fused persistent kernel. 68 single-warp blocks.
//   phase 1: blocks 0..31 -> P^CHUNK columns; blocks 32..66 -> D chunks
//   carry  : block 67 waits for all 67, runs 35-matvec chain, sets flag
//   final  : blocks 0..35 wait on flag, replay their chunk, write output
// ---------------------------------------------------------------------------
__global__ void __launch_bounds__(32, 1)
main_kernel(const float* __restrict__ TAx, const float* __restrict__ TAy,
            float* __restrict__ out)
{
    __shared__ __align__(16) float2 wbuf[2][NL];
    __shared__ __align__(16) float2 fD[CHUNK][NL];
    __shared__ __align__(16) float2 fF[CHUNK][NL];
    __shared__ __align__(16) float2 dsm[NDBLK][NL];

    const int lane = threadIdx.x;
    const int b    = blockIdx.x;
    const bool doFinal = (b < NCHUNK);

    u64 Pxx[NL], Pyy[NL];

    // ---- forcing precompute (off the critical chain) ----
    const float2 g0 = g_g0[lane];
    const float2 g1 = g_g1[lane];
    if (b >= NCOLS && b < PH1) {
        const int c = b - NCOLS;
        for (int m = 0; m < CHUNK; ++m) {
            const int k = c * CHUNK + m;
            float tax0 = TAx[k], tay0 = TAy[k];
            float tax1 = TAx[k + 1], tay1 = TAy[k + 1];
            fD[m][lane] = make_float2(
                tax0 * g0.x - tay0 * g0.y + tax1 * g1.x - tay1 * g1.y,
                tax0 * g0.y + tay0 * g0.x + tax1 * g1.y + tay1 * g1.x);
        }
    }
    const int nstepsF = doFinal ? min(CHUNK, (NF - 1) - b * CHUNK) : 0;
    if (doFinal) {
        for (int m = 0; m < nstepsF; ++m) {
            const int k = b * CHUNK + m;
            float tax0 = TAx[k], tay0 = TAy[k];
            float tax1 = TAx[k + 1], tay1 = TAy[k + 1];
            fF[m][lane] = make_float2(
                tax0 * g0.x - tay0 * g0.y + tax1 * g1.x - tay1 * g1.y,
                tax0 * g0.y + tay0 * g0.x + tax1 * g1.y + tay1 * g1.x);
        }
    }

    // ---- phase 1 ----
    if (b < PH1) {
        load_row(g_P, lane, Pxx, Pyy);
        wbuf[0][lane] = make_float2((b < NCOLS && lane == b) ? 1.0f : 0.0f, 0.0f);
        __syncwarp();
        int cur = 0;
        if (b < NCOLS) {
            for (int m = 0; m < CHUNK; ++m) {
                wmatvec(Pxx, Pyy, wbuf[cur], wbuf[cur ^ 1], lane, 0.0f, 0.0f);
                cur ^= 1;
            }
            g_PL[lane * NL + b] = wbuf[cur][lane];
        } else {
            for (int m = 0; m < CHUNK; ++m) {
                float2 f = fD[m][lane];
                wmatvec(Pxx, Pyy, wbuf[cur], wbuf[cur ^ 1], lane, f.x, f.y);
                cur ^= 1;
            }
            g_D[b - NCOLS][lane] = wbuf[cur][lane];
        }
        __threadfence();
        if (lane == 0) atomicAdd(&g_counter, 1);
    }

    // ---- carry chain (block 67) ----
    if (b == PH1) {
        if (lane == 0)
            while (atomicAdd(&g_counter, 0) < PH1) __nanosleep(32);
        __syncwarp();
        __threadfence();

        load_row(g_PL, lane, Pxx, Pyy);
        for (int c = 0; c < NDBLK; ++c) dsm[c][lane] = g_D[c][lane];

        g_C[0][lane]  = make_float2(0.0f, 0.0f);
        wbuf[0][lane] = make_float2(0.0f, 0.0f);
        __syncwarp();
        int cur = 0;
        for (int c = 0; c < NDBLK; ++c) {
            float2 d = dsm[c][lane];
            wmatvec(Pxx, Pyy, wbuf[cur], wbuf[cur ^ 1], lane, d.x, d.y);
            cur ^= 1;
            g_C[c + 1][lane] = wbuf[cur][lane];
        }
        __threadfence();
        if (lane == 0) atomicExch(&g_flag, 1);
    }

    // ---- final replay (blocks 0..35) ----
    if (doFinal) {
        if (b == 0) {
            out[lane]           = 0.0f;      // U row 0
            out[NF * NL + lane] = 0.0f;      // V row 0
        }
        if (lane == 0)
            while (atomicAdd(&g_flag, 0) == 0) __nanosleep(32);
        __syncwarp();
        __threadfence();

        wbuf[0][lane] = g_C[b][lane];
        __syncwarp();
        int cur = 0;
        for (int m = 0; m < nstepsF; ++m) {
            float2 f = fF[m][lane];
            wmatvec(Pxx, Pyy, wbuf[cur], wbuf[cur ^ 1], lane, f.x, f.y);
            cur ^= 1;
            float2 ww = wbuf[cur][lane];
            const int k = b * CHUNK + m;
            out[(k + 1) * NL + lane]           = ww.x;
            out[NF * NL + (k + 1) * NL + lane] = ww.y;
        }
    }
}

extern "C" void kernel_launch(void* const* d_in, const int* in_sizes, int n_in,
                              void* d_out, int out_size)
{
    const float* pk  = (const float*)d_in[0];
    const float* TAx = (const float*)d_in[1];
    const float* TAy = (const float*)d_in[2];
    const float* fc  = (const float*)d_in[3];
    float* out = (float*)d_out;

    setup_kernel<<<NL + 1, 32>>>(pk, fc);
    main_kernel<<<GRIDM, 32>>>(TAx, TAy, out);
}